// round 7
// baseline (speedup 1.0000x reference)
#include <cuda_runtime.h>
#include <math.h>

#define VOCAB 50257
#define HID   1024
#define H2    2048
#define H3    3072
#define MAXLEN 64
#define GRID 148
#define NT 512
#define NW (GRID * 16)          // 2368 warps
#define NUNITS16 3142           // ceil(VOCAB / 16)
#define BIG_NEG (-3.0e38f)

// ---------------- scratch ----------------
__device__ unsigned g_cnt;
__device__ unsigned g_gen;      // monotone across replays
__device__ unsigned gw0;        // Whh steal counter (reset at kernel end)
__device__ unsigned gw3;        // Wih steal counter
__device__ unsigned gw4;        // outproj steal counter
__device__ float g_logits[MAXLEN];
__device__ float g_cat[H2];
__device__ float g_xp[H2];
__device__ float g_gi[H3];
__device__ float g_gh[H3];
__device__ float g_pm[GRID];
__device__ float g_ps[GRID];

__device__ __forceinline__ float warp_sum(float v) {
#pragma unroll
    for (int o = 16; o; o >>= 1) v += __shfl_xor_sync(0xffffffffu, v, o);
    return v;
}

__device__ __forceinline__ float dot4(float4 a, float4 b) {
    return a.x * b.x + a.y * b.y + a.z * b.z + a.w * b.w;
}

__device__ __forceinline__ void lse_update(float& m, float& s, float x) {
    float M = fmaxf(m, x);
    s = s * __expf(m - M) + __expf(x - M);
    m = M;
}

__device__ __forceinline__ void lse_merge(float& m, float& s, float m2, float s2) {
    float M = fmaxf(m, m2);
    s = s * __expf(m - M) + s2 * __expf(m2 - M);
    m = M;
}

__device__ __forceinline__ int steal(unsigned* c) {
    int g = 0;
    if ((threadIdx.x & 31) == 0) g = (int)atomicAdd(c, 1u);
    return __shfl_sync(0xffffffffu, g, 0);
}

__device__ __forceinline__ void prefetch_span(const float* base, int lines, int lane) {
    const char* p = (const char*)base;
    for (int i = lane; i < lines; i += 32)
        asm volatile("prefetch.global.L2 [%0];" :: "l"(p + (size_t)i * 128));
}

// grid barrier; safe: 148 CTAs, 1/SM, all co-resident
__device__ __forceinline__ void gsync() {
    __syncthreads();
    if (threadIdx.x == 0) {
        __threadfence();
        unsigned my = *(volatile unsigned*)&g_gen;
        unsigned old = atomicAdd(&g_cnt, 1u);
        if (old == GRID - 1) {
            g_cnt = 0;
            __threadfence();
            atomicAdd(&g_gen, 1u);
        } else {
            while (*(volatile unsigned*)&g_gen == my) { }
        }
        __threadfence();
    }
    __syncthreads();
}

__global__ void __launch_bounds__(NT) k_fused(
    const int* __restrict__ inp,
    const float* __restrict__ hidden,
    const float* __restrict__ enc,
    const float* __restrict__ emb,
    const float* __restrict__ attn_W,
    const float* __restrict__ attn_b,
    const float* __restrict__ comb_W,
    const float* __restrict__ comb_b,
    const float* __restrict__ Wih,
    const float* __restrict__ Whh,
    const float* __restrict__ bih,
    const float* __restrict__ bhh,
    const float* __restrict__ out_W,
    const float* __restrict__ out_b,
    float* __restrict__ dout)
{
    __shared__ float sw[MAXLEN];
    __shared__ float spart[4][128];
    __shared__ float svec[HID];
    __shared__ float sm[NT], ss[NT];

    const int t = threadIdx.x;
    const int b = blockIdx.x;
    const int wid = t >> 5, lane = t & 31;
    const int GW = b * 16 + wid;

    const float4* h4 = (const float4*)hidden;

    // ======== Phase 0: attn logits (warps 0..63) + work-stolen Whh gates ========
    if (GW < 64) {
        const int row = GW;
        const float4* er4 = (const float4*)(emb + (size_t)inp[0] * HID);
        const float4* wr = (const float4*)(attn_W + (size_t)row * H2);
        float acc = 0.f;
#pragma unroll
        for (int i = 0; i < 16; i++) {
            int off = lane + 32 * i;
            float4 v = (i < 8) ? er4[off] : h4[off - 256];
            acc += dot4(wr[off], v);
        }
        acc = warp_sum(acc);
        if (lane == 0) g_logits[row] = acc + attn_b[row];
    }
    while (true) {
        int u = steal(&gw0);
        if (u >= H3 / 2) break;
        int r0 = 2 * u;
        const float4* w0 = (const float4*)(Whh + (size_t)r0 * HID);
        const float4* w1 = (const float4*)(Whh + (size_t)(r0 + 1) * HID);
        float a0 = 0.f, a1 = 0.f;
#pragma unroll
        for (int i = 0; i < 8; i++) {
            int off = lane + 32 * i;
            float4 v = h4[off];
            a0 += dot4(w0[off], v);
            a1 += dot4(w1[off], v);
        }
        a0 = warp_sum(a0);
        a1 = warp_sum(a1);
        if (lane == 0) {
            g_gh[r0] = a0 + bhh[r0];
            g_gh[r0 + 1] = a1 + bhh[r0 + 1];
        }
    }
    gsync();

    // ======== Phase 1: softmax+applied+cat (blocks 0..7); others prefetch out_W ========
    if (b < 8) {
        if (t < MAXLEN) sw[t] = g_logits[t];
        __syncthreads();
        if (t < 32) {
            float a = sw[t], c = sw[t + 32];
            float m = fmaxf(a, c);
#pragma unroll
            for (int o = 16; o; o >>= 1) m = fmaxf(m, __shfl_xor_sync(0xffffffffu, m, o));
            float e0 = __expf(a - m), e1 = __expf(c - m);
            float s = e0 + e1;
#pragma unroll
            for (int o = 16; o; o >>= 1) s += __shfl_xor_sync(0xffffffffu, s, o);
            sw[t] = e0 / s;
            sw[t + 32] = e1 / s;
            if (b == 0) {
                dout[VOCAB + HID + t] = sw[t];
                dout[VOCAB + HID + t + 32] = sw[t + 32];
            }
        }
        __syncthreads();
        int j = b * 128 + (t & 127);
        int isl = t >> 7;
        float a = 0.f;
#pragma unroll
        for (int k = 0; k < 16; k++) {
            int i = isl + 4 * k;
            a += sw[i] * enc[i * HID + j];
        }
        spart[isl][t & 127] = a;
        __syncthreads();
        if (t < 128) {
            float s = spart[0][t] + spart[1][t] + spart[2][t] + spart[3][t];
            g_cat[HID + j] = s;
            g_cat[j] = emb[(size_t)inp[0] * HID + j];
        }
    } else {
        // prefetch first ~18.3MB of out_W: warp W2 covers 8KB (64 lines)
        int W2 = (b - 8) * 16 + wid;             // 0..2239
        prefetch_span(out_W + (size_t)W2 * 2048, 64, lane);
    }
    gsync();

    // ======== Phase 2: combine split-K=2 (2048 warps); rest prefetch more out_W ========
    if (GW < 2048) {
        int row = GW >> 1, half = GW & 1;
        const float4* wr = (const float4*)(comb_W + (size_t)row * H2) + half * 256;
        const float4* c4 = (const float4*)g_cat + half * 256;
        float acc = 0.f;
#pragma unroll
        for (int i = 0; i < 8; i++) {
            int off = lane + 32 * i;
            acc += dot4(wr[off], c4[off]);
        }
        acc = warp_sum(acc);
        if (lane == 0) g_xp[row + half * HID] = acc;
    } else {
        // warps 2048..2367: prefetch region [18.35MB, 28.8MB): 32KB (256 lines) each
        int idx = GW - 2048;                     // 0..319
        prefetch_span(out_W + (size_t)(2240 * 2048) + (size_t)idx * 8192, 256, lane);
    }
    gsync();

    // ======== Phase 3: x = relu(p0+p1+b) ; gi = Wih@x (work-stolen, 2-row units) ========
    {
        for (int k = t; k < HID; k += NT)
            svec[k] = fmaxf(g_xp[k] + g_xp[k + HID] + comb_b[k], 0.f);
        __syncthreads();
        const float4* x4 = (const float4*)svec;
        while (true) {
            int u = steal(&gw3);
            if (u >= H3 / 2) break;
            int r0 = 2 * u;
            const float4* w0 = (const float4*)(Wih + (size_t)r0 * HID);
            const float4* w1 = (const float4*)(Wih + (size_t)(r0 + 1) * HID);
            float a0 = 0.f, a1 = 0.f;
#pragma unroll
            for (int i = 0; i < 8; i++) {
                int off = lane + 32 * i;
                float4 v = x4[off];
                a0 += dot4(w0[off], v);
                a1 += dot4(w1[off], v);
            }
            a0 = warp_sum(a0);
            a1 = warp_sum(a1);
            if (lane == 0) {
                g_gi[r0] = a0 + bih[r0];
                g_gi[r0 + 1] = a1 + bih[r0 + 1];
            }
        }
    }
    gsync();

    // ======== Phase 4: h_new (redundant) + work-stealing out-proj (16-row units) ========
    __syncthreads();
    for (int k = t; k < HID; k += NT) {
        float r = 1.f / (1.f + __expf(-(g_gi[k] + g_gh[k])));
        float z = 1.f / (1.f + __expf(-(g_gi[k + HID] + g_gh[k + HID])));
        float n = tanhf(g_gi[k + 2 * HID] + r * g_gh[k + 2 * HID]);
        float hnew = (1.f - z) * n + z * hidden[k];
        svec[k] = hnew;
        if (b == 0) dout[VOCAB + k] = hnew;
    }
    __syncthreads();
    {
        const float4* sv4 = (const float4*)svec;
        while (true) {
            int u = steal(&gw4);
            if (u >= NUNITS16) break;
#pragma unroll
            for (int p = 0; p < 2; p++) {
                int row0 = u * 16 + p * 8;
                if (row0 >= VOCAB) break;
                const float4* rp[8];
#pragma unroll
                for (int r = 0; r < 8; r++) {
                    int row = row0 + r;
                    if (row >= VOCAB) row = VOCAB - 1;
                    rp[r] = (const float4*)(out_W + (size_t)row * HID);
                }
                float acc[8];
#pragma unroll
                for (int r = 0; r < 8; r++) acc[r] = 0.f;
#pragma unroll
                for (int i = 0; i < 8; i++) {
                    int off = lane + 32 * i;
                    float4 v = sv4[off];
#pragma unroll
                    for (int r = 0; r < 8; r++) acc[r] += dot4(rp[r][off], v);
                }
#pragma unroll
                for (int r = 0; r < 8; r++) acc[r] = warp_sum(acc[r]);
                if (lane == 0) {
#pragma unroll
                    for (int r = 0; r < 8; r++) {
                        int row = row0 + r;
                        if (row < VOCAB) dout[row] = acc[r] + out_b[row];
                    }
                }
            }
        }
    }
    gsync();

    // ======== Phase 5: per-block LSE partials ========
    {
        float m = BIG_NEG, s = 0.f;
        for (int i = b * NT + t; i < VOCAB; i += GRID * NT)
            lse_update(m, s, dout[i]);
        sm[t] = m;
        ss[t] = s;
        __syncthreads();
        for (int o = NT / 2; o; o >>= 1) {
            if (t < o) lse_merge(sm[t], ss[t], sm[t + o], ss[t + o]);
            __syncthreads();
        }
        if (t == 0) { g_pm[b] = sm[0]; g_ps[b] = ss[0]; }
    }
    gsync();

    // ======== Phase 6: merge partials + subtract; reset steal counters ========
    {
        float m = BIG_NEG, s = 0.f;
        if (t < GRID) { m = g_pm[t]; s = g_ps[t]; }
        sm[t] = m;
        ss[t] = s;
        __syncthreads();
        for (int o = NT / 2; o; o >>= 1) {
            if (t < o) lse_merge(sm[t], ss[t], sm[t + o], ss[t + o]);
            __syncthreads();
        }
        float lse = sm[0] + __logf(ss[0]);
        for (int i = b * NT + t; i < VOCAB; i += GRID * NT) dout[i] -= lse;
    }
    // reset steal counters for the next graph replay (all uses are before gsyncs above)
    if (b == 0 && t == 0) { gw0 = 0; gw3 = 0; gw4 = 0; }
}

// ---------------- launcher ----------------
extern "C" void kernel_launch(void* const* d_in, const int* in_sizes, int n_in,
                              void* d_out, int out_size) {
    const int*   inp    = (const int*)d_in[0];
    const float* hidden = (const float*)d_in[1];
    const float* enc    = (const float*)d_in[2];
    const float* emb    = (const float*)d_in[3];
    const float* attn_W = (const float*)d_in[4];
    const float* attn_b = (const float*)d_in[5];
    const float* comb_W = (const float*)d_in[6];
    const float* comb_b = (const float*)d_in[7];
    const float* Wih    = (const float*)d_in[8];
    const float* Whh    = (const float*)d_in[9];
    const float* bih    = (const float*)d_in[10];
    const float* bhh    = (const float*)d_in[11];
    const float* out_W  = (const float*)d_in[12];
    const float* out_b  = (const float*)d_in[13];
    float* out = (float*)d_out;

    k_fused<<<GRID, NT>>>(inp, hidden, enc, emb, attn_W, attn_b,
                          comb_W, comb_b, Wih, Whh, bih, bhh,
                          out_W, out_b, out);
}

// round 8
// speedup vs baseline: 1.2747x; 1.2747x over previous
#include <cuda_runtime.h>
#include <math.h>

#define VOCAB 50257
#define HID   1024
#define H2    2048
#define H3    3072
#define MAXLEN 64
#define GRID 148
#define NT 512
#define NW (GRID * 16)
#define BIG_NEG (-3.0e38f)

#define ROWS_PER_BUF 16
#define NBUF 3
#define TILE_FLOATS (ROWS_PER_BUF * HID)          // 16384 floats = 64KB
#define DYN_SMEM_BYTES (NBUF * TILE_FLOATS * 4)   // 196608

// ---------------- scratch ----------------
__device__ unsigned g_cnt;
__device__ unsigned g_gen;
__device__ float g_logits[MAXLEN];
__device__ float g_cat[H2];
__device__ float g_xp[H2];
__device__ float g_gi[H3];
__device__ float g_gh[H3];
__device__ float g_pm[GRID];
__device__ float g_ps[GRID];

__device__ __forceinline__ float warp_sum(float v) {
#pragma unroll
    for (int o = 16; o; o >>= 1) v += __shfl_xor_sync(0xffffffffu, v, o);
    return v;
}

__device__ __forceinline__ float dot4(float4 a, float4 b) {
    return a.x * b.x + a.y * b.y + a.z * b.z + a.w * b.w;
}

__device__ __forceinline__ void lse_update(float& m, float& s, float x) {
    float M = fmaxf(m, x);
    s = s * __expf(m - M) + __expf(x - M);
    m = M;
}

__device__ __forceinline__ void lse_merge(float& m, float& s, float m2, float s2) {
    float M = fmaxf(m, m2);
    s = s * __expf(m - M) + s2 * __expf(m2 - M);
    m = M;
}

__device__ __forceinline__ unsigned smem_u32(const void* p) {
    return (unsigned)__cvta_generic_to_shared(p);
}

__device__ __forceinline__ void mbar_init(unsigned mbar, unsigned count) {
    asm volatile("mbarrier.init.shared.b64 [%0], %1;" :: "r"(mbar), "r"(count) : "memory");
}

__device__ __forceinline__ void mbar_expect_tx(unsigned mbar, unsigned bytes) {
    asm volatile("mbarrier.arrive.expect_tx.shared.b64 _, [%0], %1;" :: "r"(mbar), "r"(bytes) : "memory");
}

__device__ __forceinline__ void mbar_wait(unsigned mbar, unsigned parity) {
    unsigned done;
    asm volatile(
        "{\n\t.reg .pred p;\n\t"
        "mbarrier.try_wait.parity.acquire.cta.shared::cta.b64 p, [%1], %2;\n\t"
        "selp.b32 %0, 1, 0, p;\n\t}"
        : "=r"(done) : "r"(mbar), "r"(parity) : "memory");
    if (!done) {
        asm volatile(
            "{\n\t.reg .pred P1;\n\t"
            "WL_%=:\n\t"
            "mbarrier.try_wait.parity.acquire.cta.shared::cta.b64 P1, [%0], %1, 0x989680;\n\t"
            "@P1 bra.uni WD_%=;\n\t"
            "bra.uni WL_%=;\n\t"
            "WD_%=:\n\t}"
            :: "r"(mbar), "r"(parity) : "memory");
    }
}

__device__ __forceinline__ void tma_bulk_1d(unsigned dst_smem, const void* src, unsigned bytes, unsigned mbar) {
    asm volatile(
        "cp.async.bulk.shared::cta.global.mbarrier::complete_tx::bytes [%0], [%1], %2, [%3];"
        :: "r"(dst_smem), "l"(src), "r"(bytes), "r"(mbar) : "memory");
}

// grid barrier; safe: 148 CTAs, 1/SM, all co-resident
__device__ __forceinline__ void gsync() {
    __syncthreads();
    if (threadIdx.x == 0) {
        __threadfence();
        unsigned my = *(volatile unsigned*)&g_gen;
        unsigned old = atomicAdd(&g_cnt, 1u);
        if (old == GRID - 1) {
            g_cnt = 0;
            __threadfence();
            atomicAdd(&g_gen, 1u);
        } else {
            while (*(volatile unsigned*)&g_gen == my) { }
        }
        __threadfence();
    }
    __syncthreads();
}

extern __shared__ __align__(128) float dynsmem[];   // NBUF tiles of 64KB

__global__ void __launch_bounds__(NT) k_fused(
    const int* __restrict__ inp,
    const float* __restrict__ hidden,
    const float* __restrict__ enc,
    const float* __restrict__ emb,
    const float* __restrict__ attn_W,
    const float* __restrict__ attn_b,
    const float* __restrict__ comb_W,
    const float* __restrict__ comb_b,
    const float* __restrict__ Wih,
    const float* __restrict__ Whh,
    const float* __restrict__ bih,
    const float* __restrict__ bhh,
    const float* __restrict__ out_W,
    const float* __restrict__ out_b,
    float* __restrict__ dout)
{
    __shared__ float sw[MAXLEN];
    __shared__ float spart[4][128];
    __shared__ float svec[HID];
    __shared__ float sm[NT], ss[NT];
    __shared__ __align__(8) unsigned long long mbar_store[NBUF];

    const int t = threadIdx.x;
    const int b = blockIdx.x;
    const int wid = t >> 5, lane = t & 31;
    const int GW = b * 16 + wid;

    const float4* h4 = (const float4*)hidden;

    // init mbarriers for phase-4 TMA ring (fresh each call; prior phases all complete)
    if (t == 0) {
#pragma unroll
        for (int i = 0; i < NBUF; i++) mbar_init(smem_u32(&mbar_store[i]), 1);
    }

    // ======== Phase 0: attn logits (warps 0..63) || Whh gates (rest) ========
    if (GW < 64) {
        const int row = GW;
        const float4* er4 = (const float4*)(emb + (size_t)inp[0] * HID);
        const float4* wr = (const float4*)(attn_W + (size_t)row * H2);
        float acc = 0.f;
#pragma unroll
        for (int i = 0; i < 16; i++) {
            int off = lane + 32 * i;
            float4 v = (i < 8) ? er4[off] : h4[off - 256];
            acc += dot4(wr[off], v);
        }
        acc = warp_sum(acc);
        if (lane == 0) g_logits[row] = acc + attn_b[row];
    } else {
        for (int r = GW - 64; r < H3; r += NW - 64) {
            const float4* wr = (const float4*)(Whh + (size_t)r * HID);
            float acc = 0.f;
#pragma unroll
            for (int i = 0; i < 8; i++) {
                int off = lane + 32 * i;
                acc += dot4(wr[off], h4[off]);
            }
            acc = warp_sum(acc);
            if (lane == 0) g_gh[r] = acc + bhh[r];
        }
    }
    gsync();

    // ======== Phase 1: softmax + attn_applied + cat (blocks 0..7) ========
    if (b < 8) {
        if (t < MAXLEN) sw[t] = g_logits[t];
        __syncthreads();
        if (t < 32) {
            float a = sw[t], c = sw[t + 32];
            float m = fmaxf(a, c);
#pragma unroll
            for (int o = 16; o; o >>= 1) m = fmaxf(m, __shfl_xor_sync(0xffffffffu, m, o));
            float e0 = __expf(a - m), e1 = __expf(c - m);
            float s = e0 + e1;
#pragma unroll
            for (int o = 16; o; o >>= 1) s += __shfl_xor_sync(0xffffffffu, s, o);
            sw[t] = e0 / s;
            sw[t + 32] = e1 / s;
            if (b == 0) {
                dout[VOCAB + HID + t] = sw[t];
                dout[VOCAB + HID + t + 32] = sw[t + 32];
            }
        }
        __syncthreads();
        int j = b * 128 + (t & 127);
        int isl = t >> 7;
        float a = 0.f;
#pragma unroll
        for (int k = 0; k < 16; k++) {
            int i = isl + 4 * k;
            a += sw[i] * enc[i * HID + j];
        }
        spart[isl][t & 127] = a;
        __syncthreads();
        if (t < 128) {
            float s = spart[0][t] + spart[1][t] + spart[2][t] + spart[3][t];
            g_cat[HID + j] = s;
            g_cat[j] = emb[(size_t)inp[0] * HID + j];
        }
    }
    gsync();

    // ======== Phase 2: combine split-K=2 partials (2048 warps) ========
    if (GW < 2048) {
        int row = GW >> 1, half = GW & 1;
        const float4* wr = (const float4*)(comb_W + (size_t)row * H2) + half * 256;
        const float4* c4 = (const float4*)g_cat + half * 256;
        float acc = 0.f;
#pragma unroll
        for (int i = 0; i < 8; i++) {
            int off = lane + 32 * i;
            acc += dot4(wr[off], c4[off]);
        }
        acc = warp_sum(acc);
        if (lane == 0) g_xp[row + half * HID] = acc;
    }
    gsync();

    // ======== Phase 3: x = relu(p0+p1+b) ; gi = Wih@x ========
    {
        for (int k = t; k < HID; k += NT)
            svec[k] = fmaxf(g_xp[k] + g_xp[k + HID] + comb_b[k], 0.f);
        __syncthreads();
        const float4* x4 = (const float4*)svec;
        for (int r = GW; r < H3; r += NW) {
            const float4* wr = (const float4*)(Wih + (size_t)r * HID);
            float acc = 0.f;
#pragma unroll
            for (int i = 0; i < 8; i++) {
                int off = lane + 32 * i;
                acc += dot4(wr[off], x4[off]);
            }
            acc = warp_sum(acc);
            if (lane == 0) g_gi[r] = acc + bih[r];
        }
    }
    gsync();

    // ======== Phase 4: h_new (redundant) + TMA-pipelined out-proj ========
    __syncthreads();
    for (int k = t; k < HID; k += NT) {
        float r = 1.f / (1.f + __expf(-(g_gi[k] + g_gh[k])));
        float z = 1.f / (1.f + __expf(-(g_gi[k + HID] + g_gh[k + HID])));
        float n = tanhf(g_gi[k + 2 * HID] + r * g_gh[k + 2 * HID]);
        float hnew = (1.f - z) * n + z * hidden[k];
        svec[k] = hnew;
        if (b == 0) dout[VOCAB + k] = hnew;
    }
    __syncthreads();
    {
        // static contiguous slice: VOCAB = 148*339 + 85
        const int start = b * 339 + (b < 85 ? b : 85);
        const int count = 339 + (b < 85 ? 1 : 0);
        const int nbuf = (count + ROWS_PER_BUF - 1) / ROWS_PER_BUF;

        // prologue: issue first NBUF buffers
        if (t == 0) {
#pragma unroll
            for (int s = 0; s < NBUF; s++) {
                if (s < nbuf) {
                    int r0 = s * ROWS_PER_BUF;
                    int rows = count - r0; if (rows > ROWS_PER_BUF) rows = ROWS_PER_BUF;
                    unsigned bytes = (unsigned)rows * HID * 4;
                    unsigned mb = smem_u32(&mbar_store[s]);
                    mbar_expect_tx(mb, bytes);
                    tma_bulk_1d(smem_u32(&dynsmem[s * TILE_FLOATS]),
                                out_W + (size_t)(start + r0) * HID, bytes, mb);
                }
            }
        }
        __syncthreads();

        for (int s = 0; s < nbuf; s++) {
            int slot = s % NBUF;
            unsigned parity = (unsigned)((s / NBUF) & 1);
            mbar_wait(smem_u32(&mbar_store[slot]), parity);

            int lrow = s * ROWS_PER_BUF + wid;   // one row per warp
            if (wid < ROWS_PER_BUF && lrow < count) {
                const float4* rowp = (const float4*)&dynsmem[slot * TILE_FLOATS + wid * HID];
                const float4* sv4 = (const float4*)svec;
                float acc = 0.f;
#pragma unroll
                for (int i = 0; i < 8; i++) {
                    int off = lane + 32 * i;
                    acc += dot4(rowp[off], sv4[off]);
                }
                acc = warp_sum(acc);
                if (lane == 0) {
                    int grow = start + lrow;
                    dout[grow] = acc + out_b[grow];
                }
            }
            __syncthreads();   // all warps done with slot before refill
            if (t == 0 && s + NBUF < nbuf) {
                int r0 = (s + NBUF) * ROWS_PER_BUF;
                int rows = count - r0; if (rows > ROWS_PER_BUF) rows = ROWS_PER_BUF;
                unsigned bytes = (unsigned)rows * HID * 4;
                unsigned mb = smem_u32(&mbar_store[slot]);
                mbar_expect_tx(mb, bytes);
                tma_bulk_1d(smem_u32(&dynsmem[slot * TILE_FLOATS]),
                            out_W + (size_t)(start + r0) * HID, bytes, mb);
            }
        }
    }
    gsync();

    // ======== Phase 5: per-block LSE partials over logits (L2 resident) ========
    {
        float m = BIG_NEG, s = 0.f;
        for (int i = b * NT + t; i < VOCAB; i += GRID * NT)
            lse_update(m, s, dout[i]);
        sm[t] = m;
        ss[t] = s;
        __syncthreads();
        for (int o = NT / 2; o; o >>= 1) {
            if (t < o) lse_merge(sm[t], ss[t], sm[t + o], ss[t + o]);
            __syncthreads();
        }
        if (t == 0) { g_pm[b] = sm[0]; g_ps[b] = ss[0]; }
    }
    gsync();

    // ======== Phase 6: merge partials (redundant) + subtract ========
    {
        float m = BIG_NEG, s = 0.f;
        if (t < GRID) { m = g_pm[t]; s = g_ps[t]; }
        sm[t] = m;
        ss[t] = s;
        __syncthreads();
        for (int o = NT / 2; o; o >>= 1) {
            if (t < o) lse_merge(sm[t], ss[t], sm[t + o], ss[t + o]);
            __syncthreads();
        }
        float lse = sm[0] + __logf(ss[0]);
        for (int i = b * NT + t; i < VOCAB; i += GRID * NT) dout[i] -= lse;
    }
}

// ---------------- launcher ----------------
extern "C" void kernel_launch(void* const* d_in, const int* in_sizes, int n_in,
                              void* d_out, int out_size) {
    const int*   inp    = (const int*)d_in[0];
    const float* hidden = (const float*)d_in[1];
    const float* enc    = (const float*)d_in[2];
    const float* emb    = (const float*)d_in[3];
    const float* attn_W = (const float*)d_in[4];
    const float* attn_b = (const float*)d_in[5];
    const float* comb_W = (const float*)d_in[6];
    const float* comb_b = (const float*)d_in[7];
    const float* Wih    = (const float*)d_in[8];
    const float* Whh    = (const float*)d_in[9];
    const float* bih    = (const float*)d_in[10];
    const float* bhh    = (const float*)d_in[11];
    const float* out_W  = (const float*)d_in[12];
    const float* out_b  = (const float*)d_in[13];
    float* out = (float*)d_out;

    cudaFuncSetAttribute(k_fused, cudaFuncAttributeMaxDynamicSharedMemorySize, DYN_SMEM_BYTES);
    k_fused<<<GRID, NT, DYN_SMEM_BYTES>>>(inp, hidden, enc, emb, attn_W, attn_b,
                                          comb_W, comb_b, Wih, Whh, bih, bhh,
                                          out_W, out_b, out);
}

// round 9
// speedup vs baseline: 1.4275x; 1.1199x over previous
#include <cuda_runtime.h>
#include <math.h>

#define VOCAB 50257
#define HID   1024
#define H2    2048
#define H3    3072
#define MAXLEN 64
#define GRID 148
#define NT 512
#define NW (GRID * 16)          // 2368 warps
#define NGROUPS 6283            // ceil(VOCAB / 8)
#define BIG_NEG (-3.0e38f)

// ---------------- scratch ----------------
__device__ unsigned g_cnt;
__device__ unsigned g_gen;
__device__ unsigned g_work;
__device__ float g_logits[MAXLEN];
__device__ float g_cat[H2];
__device__ float g_xp[H2];
__device__ float g_gi[H3];
__device__ float g_gh[H3];
__device__ float g_pm[GRID];
__device__ float g_ps[GRID];

__device__ __forceinline__ float warp_sum(float v) {
#pragma unroll
    for (int o = 16; o; o >>= 1) v += __shfl_xor_sync(0xffffffffu, v, o);
    return v;
}

__device__ __forceinline__ float dot4(float4 a, float4 b) {
    return a.x * b.x + a.y * b.y + a.z * b.z + a.w * b.w;
}

__device__ __forceinline__ void lse_update(float& m, float& s, float x) {
    float M = fmaxf(m, x);
    s = s * __expf(m - M) + __expf(x - M);
    m = M;
}

__device__ __forceinline__ void lse_merge(float& m, float& s, float m2, float s2) {
    float M = fmaxf(m, m2);
    s = s * __expf(m - M) + s2 * __expf(m2 - M);
    m = M;
}

// grid barrier; safe: GRID (148) <= #SMs so all CTAs co-resident
__device__ __forceinline__ void gsync() {
    __syncthreads();
    if (threadIdx.x == 0) {
        __threadfence();
        unsigned my = *(volatile unsigned*)&g_gen;
        unsigned old = atomicAdd(&g_cnt, 1u);
        if (old == GRID - 1) {
            g_cnt = 0;
            __threadfence();
            atomicAdd(&g_gen, 1u);
        } else {
            while (*(volatile unsigned*)&g_gen == my) { }
        }
        __threadfence();
    }
    __syncthreads();
}

__global__ void __launch_bounds__(NT, 1) k_fused(
    const int* __restrict__ inp,
    const float* __restrict__ hidden,
    const float* __restrict__ enc,
    const float* __restrict__ emb,
    const float* __restrict__ attn_W,
    const float* __restrict__ attn_b,
    const float* __restrict__ comb_W,
    const float* __restrict__ comb_b,
    const float* __restrict__ Wih,
    const float* __restrict__ Whh,
    const float* __restrict__ bih,
    const float* __restrict__ bhh,
    const float* __restrict__ out_W,
    const float* __restrict__ out_b,
    float* __restrict__ dout)
{
    __shared__ float sw[MAXLEN];
    __shared__ float spart[4][128];
    __shared__ float svec[HID];       // phase3: x ; phase4: h_new
    __shared__ float rm[16], rs[16];
    __shared__ float sm[NT], ss[NT];

    const int t = threadIdx.x;
    const int b = blockIdx.x;
    const int wid = t >> 5, lane = t & 31;
    const int GW = b * 16 + wid;

    const float4* h4 = (const float4*)hidden;

    // ======== Phase 0: attn logits (warps 0..63) || Whh gates (rest) ========
    if (b == 0 && t == 0) g_work = 0;   // ordered by gsyncs before phase 4
    if (GW < 64) {
        const int row = GW;
        const float4* er4 = (const float4*)(emb + (size_t)inp[0] * HID);
        const float4* wr = (const float4*)(attn_W + (size_t)row * H2);
        float acc = 0.f;
#pragma unroll
        for (int i = 0; i < 16; i++) {
            int off = lane + 32 * i;
            float4 v = (i < 8) ? er4[off] : h4[off - 256];
            acc += dot4(wr[off], v);
        }
        acc = warp_sum(acc);
        if (lane == 0) g_logits[row] = acc + attn_b[row];
    } else {
        for (int r = GW - 64; r < H3; r += NW - 64) {
            const float4* wr = (const float4*)(Whh + (size_t)r * HID);
            float acc = 0.f;
#pragma unroll
            for (int i = 0; i < 8; i++) {
                int off = lane + 32 * i;
                acc += dot4(wr[off], h4[off]);
            }
            acc = warp_sum(acc);
            if (lane == 0) g_gh[r] = acc + bhh[r];
        }
    }
    gsync();

    // ======== Phase 1: softmax + attn_applied + cat (blocks 0..7) ========
    //          idle blocks: one bulk L2 prefetch instruction per warp over out_W
    if (b < 8) {
        if (t < MAXLEN) sw[t] = g_logits[t];
        __syncthreads();
        if (t < 32) {
            float a = sw[t], c = sw[t + 32];
            float m = fmaxf(a, c);
#pragma unroll
            for (int o = 16; o; o >>= 1) m = fmaxf(m, __shfl_xor_sync(0xffffffffu, m, o));
            float e0 = __expf(a - m), e1 = __expf(c - m);
            float s = e0 + e1;
#pragma unroll
            for (int o = 16; o; o >>= 1) s += __shfl_xor_sync(0xffffffffu, s, o);
            sw[t] = e0 / s;
            sw[t + 32] = e1 / s;
            if (b == 0) {
                dout[VOCAB + HID + t] = sw[t];
                dout[VOCAB + HID + t + 32] = sw[t + 32];
            }
        }
        __syncthreads();
        int j = b * 128 + (t & 127);
        int isl = t >> 7;                 // 0..3
        float a = 0.f;
#pragma unroll
        for (int k = 0; k < 16; k++) {
            int i = isl + 4 * k;
            a += sw[i] * enc[i * HID + j];
        }
        spart[isl][t & 127] = a;
        __syncthreads();
        if (t < 128) {
            float s = spart[0][t] + spart[1][t] + spart[2][t] + spart[3][t];
            g_cat[HID + j] = s;
            g_cat[j] = emb[(size_t)inp[0] * HID + j];
        }
    } else if (lane == 0) {
        // fire-and-forget 48KB bulk prefetch: 140 blocks * 16 warps = 105MB of out_W
        int W2 = (b - 8) * 16 + wid;       // 0..2239
        const char* src = (const char*)out_W + (size_t)W2 * 49152;
        asm volatile("cp.async.bulk.prefetch.L2.global [%0], %1;"
                     :: "l"(src), "r"(49152) : "memory");
    }
    gsync();

    // ======== Phase 2: combine split-K=2 partials (2048 warps) ========
    if (GW < 2048) {
        int row = GW >> 1, half = GW & 1;
        const float4* wr = (const float4*)(comb_W + (size_t)row * H2) + half * 256;
        const float4* c4 = (const float4*)g_cat + half * 256;
        float acc = 0.f;
#pragma unroll
        for (int i = 0; i < 8; i++) {
            int off = lane + 32 * i;
            acc += dot4(wr[off], c4[off]);
        }
        acc = warp_sum(acc);
        if (lane == 0) g_xp[row + half * HID] = acc;
    }
    gsync();

    // ======== Phase 3: x = relu(p0+p1+b) (per-block smem) ; gi = Wih@x ========
    {
        for (int k = t; k < HID; k += NT)
            svec[k] = fmaxf(g_xp[k] + g_xp[k + HID] + comb_b[k], 0.f);
        __syncthreads();
        const float4* x4 = (const float4*)svec;
        for (int r = GW; r < H3; r += NW) {
            const float4* wr = (const float4*)(Wih + (size_t)r * HID);
            float acc = 0.f;
#pragma unroll
            for (int i = 0; i < 8; i++) {
                int off = lane + 32 * i;
                acc += dot4(wr[off], x4[off]);
            }
            acc = warp_sum(acc);
            if (lane == 0) g_gi[r] = acc + bih[r];
        }
    }
    gsync();

    // ======== Phase 4: h_new (redundant) + work-stealing out-proj + online LSE ========
    __syncthreads();   // svec reuse: all phase-3 readers done (gsync above)
    for (int k = t; k < HID; k += NT) {
        float r = 1.f / (1.f + __expf(-(g_gi[k] + g_gh[k])));
        float z = 1.f / (1.f + __expf(-(g_gi[k + HID] + g_gh[k + HID])));
        float n = tanhf(g_gi[k + 2 * HID] + r * g_gh[k + 2 * HID]);
        float hnew = (1.f - z) * n + z * hidden[k];
        svec[k] = hnew;
        if (b == 0) dout[VOCAB + k] = hnew;
    }
    __syncthreads();
    {
        const float4* sv4 = (const float4*)svec;
        float wm = BIG_NEG, ws = 0.f;
        while (true) {
            int g;
            if (lane == 0) g = (int)atomicAdd(&g_work, 1u);
            g = __shfl_sync(0xffffffffu, g, 0);
            if (g >= NGROUPS) break;
            int row0 = g * 8;
            const float4* rp[8];
#pragma unroll
            for (int r = 0; r < 8; r++) {
                int row = row0 + r;
                if (row >= VOCAB) row = VOCAB - 1;
                rp[r] = (const float4*)(out_W + (size_t)row * HID);
            }
            float acc[8];
#pragma unroll
            for (int r = 0; r < 8; r++) acc[r] = 0.f;
#pragma unroll
            for (int i = 0; i < 8; i++) {
                int off = lane + 32 * i;
                float4 v = sv4[off];
#pragma unroll
                for (int r = 0; r < 8; r++) acc[r] += dot4(rp[r][off], v);
            }
#pragma unroll
            for (int r = 0; r < 8; r++) acc[r] = warp_sum(acc[r]);
            if (lane == 0) {
#pragma unroll
                for (int r = 0; r < 8; r++) {
                    int row = row0 + r;
                    if (row < VOCAB) {
                        float l = acc[r] + out_b[row];
                        dout[row] = l;
                        lse_update(wm, ws, l);
                    }
                }
            }
        }
        if (lane == 0) { rm[wid] = wm; rs[wid] = ws; }
    }
    __syncthreads();
    if (t == 0) {
        float m = BIG_NEG, s = 0.f;
#pragma unroll
        for (int i = 0; i < 16; i++) lse_merge(m, s, rm[i], rs[i]);
        g_pm[b] = m;
        g_ps[b] = s;
    }
    gsync();

    // ======== Phase 5: merge partials (redundant) + subtract ========
    {
        float m = BIG_NEG, s = 0.f;
        if (t < GRID) { m = g_pm[t]; s = g_ps[t]; }
        sm[t] = m;
        ss[t] = s;
        __syncthreads();
        for (int o = 128; o; o >>= 1) {
            if (t < o) lse_merge(sm[t], ss[t], sm[t + o], ss[t + o]);
            __syncthreads();
        }
        float lse = sm[0] + __logf(ss[0]);
        for (int i = b * NT + t; i < VOCAB; i += GRID * NT) dout[i] -= lse;
    }
}

// ---------------- launcher ----------------
extern "C" void kernel_launch(void* const* d_in, const int* in_sizes, int n_in,
                              void* d_out, int out_size) {
    const int*   inp    = (const int*)d_in[0];
    const float* hidden = (const float*)d_in[1];
    const float* enc    = (const float*)d_in[2];
    const float* emb    = (const float*)d_in[3];
    const float* attn_W = (const float*)d_in[4];
    const float* attn_b = (const float*)d_in[5];
    const float* comb_W = (const float*)d_in[6];
    const float* comb_b = (const float*)d_in[7];
    const float* Wih    = (const float*)d_in[8];
    const float* Whh    = (const float*)d_in[9];
    const float* bih    = (const float*)d_in[10];
    const float* bhh    = (const float*)d_in[11];
    const float* out_W  = (const float*)d_in[12];
    const float* out_b  = (const float*)d_in[13];
    float* out = (float*)d_out;

    k_fused<<<GRID, NT>>>(inp, hidden, enc, emb, attn_W, attn_b,
                          comb_W, comb_b, Wih, Whh, bih, bhh,
                          out_W, out_b, out);
}